// round 4
// baseline (speedup 1.0000x reference)
#include <cuda_runtime.h>
#include <cstdint>

#define D128 128
#define MAXN 50000
#define AS_STRIDE 132   // 128 rows + 4 pad (132*4B = 528B, 16B-aligned stride)

// ---------------- scratch (no cudaMalloc allowed) ----------------
__device__ float g_H[MAXN * D128];    // GEMM output (gather source for scatter)
__device__ float g_O1[MAXN * D128];   // layer-1 aggregated output
__device__ int   g_deg[MAXN];
__device__ float g_dinv[MAXN];
__device__ float g_sum[D128];
__device__ float g_sumsq[D128];
__device__ float g_scale[D128];
__device__ float g_bias[D128];

// ---------------- init: deg=1 (self loop), zero BN sums ----------------
__global__ void k_init(int N) {
    int i = blockIdx.x * blockDim.x + threadIdx.x;
    if (i < N) g_deg[i] = 1;
    if (i < D128) { g_sum[i] = 0.f; g_sumsq[i] = 0.f; }
}

__global__ void k_deg(const int* __restrict__ dst, int E) {
    int e = blockIdx.x * blockDim.x + threadIdx.x;
    if (e < E) atomicAdd(&g_deg[dst[e]], 1);
}

__global__ void k_dinv(int N) {
    int i = blockIdx.x * blockDim.x + threadIdx.x;
    if (i < N) g_dinv[i] = rsqrtf((float)g_deg[i]);
}

// ---------------- GEMM + fused self-loop epilogue ----------------
// 128 rows x 128 cols per block, 256 threads, 8x8 micro-tile.
// Full W in smem (64KB) + double-buffered transposed A stage (8 k-slice).
// Optional fused BN-affine+ReLU on input (scl non-null).
// Writes H = A@W  and  O = bias + H*dinv^2.
__global__ __launch_bounds__(256, 2) void k_gemm3(
    const float* __restrict__ A, const float* __restrict__ W,
    float* __restrict__ H, float* __restrict__ O,
    const float* __restrict__ bias, int N,
    const float* __restrict__ scl, const float* __restrict__ bia)
{
    extern __shared__ float smem[];
    float* Ws = smem;                        // [128][128]
    float* As = smem + 128 * 128;            // [2][8][AS_STRIDE]

    const int tid  = threadIdx.x;
    const int brow = blockIdx.x * 128;
    const int tx   = tid & 15;               // cols tx*8 .. tx*8+7
    const int ty   = tid >> 4;               // rows ty*8 .. ty*8+7

    // ---- load entire W into shared (coalesced float4) ----
    {
        const float4* Wv = (const float4*)W;
        float4* Wsv = (float4*)Ws;
        #pragma unroll
        for (int i = 0; i < 16; i++)
            Wsv[i * 256 + tid] = Wv[i * 256 + tid];
    }

    // ---- A loader mapping: one float4 per thread per 8-k chunk ----
    const int lrow = tid >> 1;               // 0..127
    const int half = tid & 1;                // which float4 of the chunk
    const int grow_ld = brow + lrow;
    const bool ld_ok = (grow_ld < N);
    const float4* Arow = (const float4*)(A + (size_t)grow_ld * D128);
    const int kb = half * 4;

    // first chunk prefetch + stage
    float4 av = make_float4(0.f, 0.f, 0.f, 0.f);
    if (ld_ok) av = Arow[half];
    if (scl != nullptr) {
        int f = kb;
        av.x = fmaxf(fmaf(av.x, scl[f + 0], bia[f + 0]), 0.f);
        av.y = fmaxf(fmaf(av.y, scl[f + 1], bia[f + 1]), 0.f);
        av.z = fmaxf(fmaf(av.z, scl[f + 2], bia[f + 2]), 0.f);
        av.w = fmaxf(fmaf(av.w, scl[f + 3], bia[f + 3]), 0.f);
    }
    As[(kb + 0) * AS_STRIDE + lrow] = av.x;
    As[(kb + 1) * AS_STRIDE + lrow] = av.y;
    As[(kb + 2) * AS_STRIDE + lrow] = av.z;
    As[(kb + 3) * AS_STRIDE + lrow] = av.w;
    __syncthreads();   // W + first A chunk ready

    float acc[8][8];
    #pragma unroll
    for (int r = 0; r < 8; r++)
        #pragma unroll
        for (int c = 0; c < 8; c++) acc[r][c] = 0.f;

    int buf = 0;
    #pragma unroll 1
    for (int ksi = 0; ksi < 16; ksi++) {
        const int ks = ksi * 8;

        // prefetch next chunk (global -> regs), overlaps with compute below
        float4 avn;
        if (ksi < 15) {
            avn = make_float4(0.f, 0.f, 0.f, 0.f);
            if (ld_ok) avn = Arow[((ks + 8) >> 2) + half];
            if (scl != nullptr) {
                int f = ks + 8 + kb;
                avn.x = fmaxf(fmaf(avn.x, scl[f + 0], bia[f + 0]), 0.f);
                avn.y = fmaxf(fmaf(avn.y, scl[f + 1], bia[f + 1]), 0.f);
                avn.z = fmaxf(fmaf(avn.z, scl[f + 2], bia[f + 2]), 0.f);
                avn.w = fmaxf(fmaf(avn.w, scl[f + 3], bia[f + 3]), 0.f);
            }
        }

        const float* Ab = As + buf * (8 * AS_STRIDE);
        #pragma unroll
        for (int kk = 0; kk < 8; kk++) {
            const float* ap = Ab + kk * AS_STRIDE + ty * 8;
            float4 a0 = *(const float4*)(ap);
            float4 a1 = *(const float4*)(ap + 4);
            const float* wp = &Ws[(ks + kk) * D128 + tx * 8];
            float4 w0 = *(const float4*)(wp);
            float4 w1 = *(const float4*)(wp + 4);
            float a[8] = {a0.x, a0.y, a0.z, a0.w, a1.x, a1.y, a1.z, a1.w};
            float w[8] = {w0.x, w0.y, w0.z, w0.w, w1.x, w1.y, w1.z, w1.w};
            #pragma unroll
            for (int r = 0; r < 8; r++)
                #pragma unroll
                for (int c = 0; c < 8; c++)
                    acc[r][c] = fmaf(a[r], w[c], acc[r][c]);
        }

        if (ksi < 15) {
            float* Ab2 = As + (1 - buf) * (8 * AS_STRIDE);
            Ab2[(kb + 0) * AS_STRIDE + lrow] = avn.x;
            Ab2[(kb + 1) * AS_STRIDE + lrow] = avn.y;
            Ab2[(kb + 2) * AS_STRIDE + lrow] = avn.z;
            Ab2[(kb + 3) * AS_STRIDE + lrow] = avn.w;
            __syncthreads();
            buf ^= 1;
        }
    }

    // ---- epilogue: H = acc,  O = bias + acc * dinv^2 ----
    const float4* Bv = (const float4*)bias;
    float4 bb0 = Bv[tx * 2];
    float4 bb1 = Bv[tx * 2 + 1];

    #pragma unroll
    for (int r = 0; r < 8; r++) {
        int grow = brow + ty * 8 + r;
        if (grow >= N) break;
        float di = g_dinv[grow];
        float wgt = di * di;
        float4 h0 = make_float4(acc[r][0], acc[r][1], acc[r][2], acc[r][3]);
        float4 h1 = make_float4(acc[r][4], acc[r][5], acc[r][6], acc[r][7]);
        float4* Hp = (float4*)(H + (size_t)grow * D128) + tx * 2;
        Hp[0] = h0;
        Hp[1] = h1;
        float4 o0, o1;
        o0.x = fmaf(h0.x, wgt, bb0.x); o0.y = fmaf(h0.y, wgt, bb0.y);
        o0.z = fmaf(h0.z, wgt, bb0.z); o0.w = fmaf(h0.w, wgt, bb0.w);
        o1.x = fmaf(h1.x, wgt, bb1.x); o1.y = fmaf(h1.y, wgt, bb1.y);
        o1.z = fmaf(h1.z, wgt, bb1.z); o1.w = fmaf(h1.w, wgt, bb1.w);
        float4* Op = (float4*)(O + (size_t)grow * D128) + tx * 2;
        Op[0] = o0;
        Op[1] = o1;
    }
}

// ---------------- edge scatter: O[dst] += H[src] * dinv[src]*dinv[dst] ----------------
__device__ __forceinline__ void red_add_v4(float* p, float a, float b, float c, float d) {
    asm volatile("red.global.add.v4.f32 [%0], {%1,%2,%3,%4};"
                 :: "l"(p), "f"(a), "f"(b), "f"(c), "f"(d) : "memory");
}

__global__ __launch_bounds__(256) void k_scatter(
    const float* __restrict__ H, float* __restrict__ O,
    const int* __restrict__ src, const int* __restrict__ dst, int E)
{
    int warp = (blockIdx.x * blockDim.x + threadIdx.x) >> 5;
    int lane = threadIdx.x & 31;
    if (warp >= E) return;
    int s = src[warp];
    int d = dst[warp];
    float nrm = g_dinv[s] * g_dinv[d];
    float4 v = ((const float4*)(H + (size_t)s * D128))[lane];
    float* p = O + (size_t)d * D128 + lane * 4;
    red_add_v4(p, v.x * nrm, v.y * nrm, v.z * nrm, v.w * nrm);
}

// ---------------- BatchNorm reduce ----------------
__global__ __launch_bounds__(256) void k_bnreduce(const float* __restrict__ H, int N) {
    int f    = threadIdx.x & 127;
    int half = threadIdx.x >> 7;
    float s = 0.f, s2 = 0.f;
    for (int row = blockIdx.x * 2 + half; row < N; row += gridDim.x * 2) {
        float v = H[(size_t)row * D128 + f];
        s += v;
        s2 = fmaf(v, v, s2);
    }
    __shared__ float sh[256], sh2[256];
    sh[threadIdx.x] = s; sh2[threadIdx.x] = s2;
    __syncthreads();
    if (threadIdx.x < 128) {
        atomicAdd(&g_sum[f],   sh[f] + sh[f + 128]);
        atomicAdd(&g_sumsq[f], sh2[f] + sh2[f + 128]);
    }
}

__global__ void k_bnfinal(const float* __restrict__ gamma, const float* __restrict__ beta, int N) {
    int f = threadIdx.x;
    if (f >= D128) return;
    float inv_n = 1.0f / (float)N;
    float mu  = g_sum[f] * inv_n;
    float var = g_sumsq[f] * inv_n - mu * mu;
    float rstd = rsqrtf(var + 1e-5f);
    float s = rstd * gamma[f];
    g_scale[f] = s;
    g_bias[f]  = beta[f] - mu * s;
}

// ---------------- launch ----------------
extern "C" void kernel_launch(void* const* d_in, const int* in_sizes, int n_in,
                              void* d_out, int out_size)
{
    const float* x     = (const float*)d_in[0];
    const int*   eidx  = (const int*)d_in[1];
    const float* W1    = (const float*)d_in[2];
    const float* b1    = (const float*)d_in[3];
    const float* gamma = (const float*)d_in[4];
    const float* beta  = (const float*)d_in[5];
    const float* W2    = (const float*)d_in[6];
    const float* b2    = (const float*)d_in[7];
    float*       out   = (float*)d_out;

    const int N = in_sizes[0] / D128;          // 50000
    const int E = in_sizes[1] / 2;             // 800000
    const int* src = eidx;
    const int* dst = eidx + E;

    float* H;  cudaGetSymbolAddress((void**)&H,  g_H);
    float* O1; cudaGetSymbolAddress((void**)&O1, g_O1);
    float* scl; cudaGetSymbolAddress((void**)&scl, g_scale);
    float* bia; cudaGetSymbolAddress((void**)&bia, g_bias);

    const int GEMM_SMEM = (128 * 128 + 2 * 8 * AS_STRIDE) * 4;   // 73984 B
    cudaFuncSetAttribute(k_gemm3, cudaFuncAttributeMaxDynamicSharedMemorySize, GEMM_SMEM);

    const int TPB = 256;
    int gridN  = (N + TPB - 1) / TPB;
    int gridE  = (E + TPB - 1) / TPB;
    long long lanes = (long long)E * 32;
    int gridEw = (int)((lanes + TPB - 1) / TPB);   // 1 warp per edge
    int gridG  = (N + 127) / 128;

    k_init<<<gridN, TPB>>>(N);
    k_deg<<<gridE, TPB>>>(dst, E);
    k_dinv<<<gridN, TPB>>>(N);

    // layer 1: GEMM + fused self-loop init
    k_gemm3<<<gridG, 256, GEMM_SMEM>>>(x, W1, H, O1, b1, N, nullptr, nullptr);
    k_scatter<<<gridEw, TPB>>>(H, O1, src, dst, E);

    // batchnorm stats -> scale/bias
    k_bnreduce<<<256, TPB>>>(O1, N);
    k_bnfinal<<<1, 128>>>(gamma, beta, N);

    // layer 2: BN+ReLU fused into GEMM input, self-loop fused into epilogue
    k_gemm3<<<gridG, 256, GEMM_SMEM>>>(O1, W2, H, out, b2, N, scl, bia);
    k_scatter<<<gridEw, TPB>>>(H, out, src, dst, E);
}

// round 7
// speedup vs baseline: 1.1662x; 1.1662x over previous
#include <cuda_runtime.h>
#include <cuda_bf16.h>
#include <cstdint>

#define D128 128
#define MAXN 50000
#define WSTR 68              // padded word stride (64 k-pair words + 4 pad)

// ---------------- scratch ----------------
__device__ float    g_H[MAXN * D128];
__device__ float    g_O1[MAXN * D128];
__device__ int      g_deg[MAXN];
__device__ float    g_dinv[MAXN];
__device__ float    g_sum[D128];
__device__ float    g_sumsq[D128];
__device__ float    g_scale[D128];
__device__ float    g_bias[D128];
__device__ uint32_t g_Wth[2 * 128 * 64];   // W^T hi, bf16 k-pair packed [slot][n][p]
__device__ uint32_t g_Wtl[2 * 128 * 64];   // W^T lo

// ---------------- helpers ----------------
__device__ __forceinline__ uint32_t pack_bf16(float f0, float f1) {
    __nv_bfloat162 h = __floats2bfloat162_rn(f0, f1);   // .x low half
    return *reinterpret_cast<uint32_t*>(&h);
}

// ---------------- init / degree ----------------
__global__ void k_init(int N) {
    int i = blockIdx.x * blockDim.x + threadIdx.x;
    if (i < N) g_deg[i] = 1;
    if (i < D128) { g_sum[i] = 0.f; g_sumsq[i] = 0.f; }
}
__global__ void k_deg(const int* __restrict__ dst, int E) {
    int e = blockIdx.x * blockDim.x + threadIdx.x;
    if (e < E) atomicAdd(&g_deg[dst[e]], 1);
}
__global__ void k_dinv(int N) {
    int i = blockIdx.x * blockDim.x + threadIdx.x;
    if (i < N) g_dinv[i] = rsqrtf((float)g_deg[i]);
}

// ---------------- both W -> transposed bf16 hi/lo split ----------------
// slot s, word (n, p) = pack(W[2p][n], W[2p+1][n])
__global__ void k_wsplit2(const float* __restrict__ W1, const float* __restrict__ W2) {
    int idx = blockIdx.x * blockDim.x + threadIdx.x;
    if (idx >= 2 * 128 * 64) return;
    int slot = idx >> 13;
    int loc  = idx & 8191;
    int n = loc >> 6, p = loc & 63;
    const float* W = slot ? W2 : W1;
    float w0 = W[(2 * p) * D128 + n];
    float w1 = W[(2 * p + 1) * D128 + n];
    __nv_bfloat16 h0 = __float2bfloat16_rn(w0);
    __nv_bfloat16 h1 = __float2bfloat16_rn(w1);
    float l0 = w0 - __bfloat162float(h0);
    float l1 = w1 - __bfloat162float(h1);
    g_Wth[idx] = pack_bf16(__bfloat162float(h0), __bfloat162float(h1));
    g_Wtl[idx] = pack_bf16(l0, l1);
}

// ---------------- tensor-core GEMM + fused self-loop epilogue ----------------
// 64 rows/block, 128 threads (4 warps x 16 rows). 3-term bf16 split MMA.
// Writes H = A@W, O = bias + H*dinv^2. Optional BN+ReLU on input.
#define MMA3(accp, a0,a1,a2,a3, b0,b1) \
    asm volatile("mma.sync.aligned.m16n8k16.row.col.f32.bf16.bf16.f32 " \
        "{%0,%1,%2,%3}, {%4,%5,%6,%7}, {%8,%9}, {%0,%1,%2,%3};" \
        : "+f"((accp)[0]), "+f"((accp)[1]), "+f"((accp)[2]), "+f"((accp)[3]) \
        : "r"(a0), "r"(a1), "r"(a2), "r"(a3), "r"(b0), "r"(b1))

__global__ __launch_bounds__(128) void k_gemm_tc(
    const float* __restrict__ A,
    float* __restrict__ H, float* __restrict__ O,
    const float* __restrict__ bias, int N, int wslot,
    const float* __restrict__ scl, const float* __restrict__ bia)
{
    extern __shared__ uint32_t sm[];
    uint32_t* WH = sm;                 // [128][WSTR]
    uint32_t* WL = sm + 128 * WSTR;
    uint32_t* AH = sm + 256 * WSTR;    // [64][WSTR]
    uint32_t* AL = sm + 256 * WSTR + 64 * WSTR;

    const int tid  = threadIdx.x;
    const int brow = blockIdx.x * 64;

    // ---- load W tiles (coalesced uint4, re-strided into padded smem) ----
    {
        const uint4* Wg  = (const uint4*)(g_Wth + wslot * 8192);
        const uint4* Wg2 = (const uint4*)(g_Wtl + wslot * 8192);
        #pragma unroll
        for (int i = 0; i < 16; i++) {
            int v = tid + i * 128;         // uint4 index 0..2047
            int w = v * 4;
            int r = w >> 6, c = w & 63;
            uint4 q = Wg[v];
            uint32_t* p = WH + r * WSTR + c;
            p[0] = q.x; p[1] = q.y; p[2] = q.z; p[3] = q.w;
            uint4 q2 = Wg2[v];
            uint32_t* p2 = WL + r * WSTR + c;
            p2[0] = q2.x; p2[1] = q2.y; p2[2] = q2.z; p2[3] = q2.w;
        }
    }

    // ---- load A tile, optional BN+ReLU, split to bf16 hi/lo ----
    #pragma unroll
    for (int i = 0; i < 16; i++) {
        int v = tid + i * 128;             // float4 index over [64][32]
        int r = v >> 5, c4 = v & 31;
        int grow = brow + r;
        float4 x = make_float4(0.f, 0.f, 0.f, 0.f);
        if (grow < N) x = ((const float4*)(A + (size_t)grow * D128))[c4];
        if (scl != nullptr) {
            int f = c4 * 4;
            x.x = fmaxf(fmaf(x.x, scl[f + 0], bia[f + 0]), 0.f);
            x.y = fmaxf(fmaf(x.y, scl[f + 1], bia[f + 1]), 0.f);
            x.z = fmaxf(fmaf(x.z, scl[f + 2], bia[f + 2]), 0.f);
            x.w = fmaxf(fmaf(x.w, scl[f + 3], bia[f + 3]), 0.f);
        }
        __nv_bfloat16 hx = __float2bfloat16_rn(x.x);
        __nv_bfloat16 hy = __float2bfloat16_rn(x.y);
        __nv_bfloat16 hz = __float2bfloat16_rn(x.z);
        __nv_bfloat16 hw = __float2bfloat16_rn(x.w);
        float lx = x.x - __bfloat162float(hx);
        float ly = x.y - __bfloat162float(hy);
        float lz = x.z - __bfloat162float(hz);
        float lw = x.w - __bfloat162float(hw);
        int base = r * WSTR + 2 * c4;
        AH[base]     = pack_bf16(__bfloat162float(hx), __bfloat162float(hy));
        AH[base + 1] = pack_bf16(__bfloat162float(hz), __bfloat162float(hw));
        AL[base]     = pack_bf16(lx, ly);
        AL[base + 1] = pack_bf16(lz, lw);
    }
    __syncthreads();

    const int lane = tid & 31, warp = tid >> 5;
    const int g = lane >> 2, t = lane & 3;
    const int wrow = warp * 16;

    float acc[16][4];
    #pragma unroll
    for (int nt = 0; nt < 16; nt++)
        #pragma unroll
        for (int j = 0; j < 4; j++) acc[nt][j] = 0.f;

    #pragma unroll
    for (int ks = 0; ks < 8; ks++) {
        const int kp = ks * 8;
        uint32_t ah0 = AH[(wrow + g)     * WSTR + kp + t];
        uint32_t ah1 = AH[(wrow + g + 8) * WSTR + kp + t];
        uint32_t ah2 = AH[(wrow + g)     * WSTR + kp + t + 4];
        uint32_t ah3 = AH[(wrow + g + 8) * WSTR + kp + t + 4];
        uint32_t al0 = AL[(wrow + g)     * WSTR + kp + t];
        uint32_t al1 = AL[(wrow + g + 8) * WSTR + kp + t];
        uint32_t al2 = AL[(wrow + g)     * WSTR + kp + t + 4];
        uint32_t al3 = AL[(wrow + g + 8) * WSTR + kp + t + 4];
        #pragma unroll
        for (int nt = 0; nt < 16; nt++) {
            int n = nt * 8 + g;
            uint32_t bh0 = WH[n * WSTR + kp + t];
            uint32_t bh1 = WH[n * WSTR + kp + t + 4];
            uint32_t bl0 = WL[n * WSTR + kp + t];
            uint32_t bl1 = WL[n * WSTR + kp + t + 4];
            MMA3(acc[nt], ah0, ah1, ah2, ah3, bh0, bh1);
            MMA3(acc[nt], ah0, ah1, ah2, ah3, bl0, bl1);
            MMA3(acc[nt], al0, al1, al2, al3, bh0, bh1);
        }
    }

    // ---- epilogue: H = acc, O = bias + acc*dinv^2 ----
    const int r0 = brow + wrow + g;
    const int r1 = r0 + 8;
    float w0 = 0.f, w1 = 0.f;
    if (r0 < N) { float d = g_dinv[r0]; w0 = d * d; }
    if (r1 < N) { float d = g_dinv[r1]; w1 = d * d; }

    #pragma unroll
    for (int nt = 0; nt < 16; nt++) {
        int col = nt * 8 + 2 * t;
        float bx = bias[col], by = bias[col + 1];
        if (r0 < N) {
            float2 h = make_float2(acc[nt][0], acc[nt][1]);
            *(float2*)(H + (size_t)r0 * D128 + col) = h;
            *(float2*)(O + (size_t)r0 * D128 + col) =
                make_float2(fmaf(h.x, w0, bx), fmaf(h.y, w0, by));
        }
        if (r1 < N) {
            float2 h = make_float2(acc[nt][2], acc[nt][3]);
            *(float2*)(H + (size_t)r1 * D128 + col) = h;
            *(float2*)(O + (size_t)r1 * D128 + col) =
                make_float2(fmaf(h.x, w1, bx), fmaf(h.y, w1, by));
        }
    }
}

// ---------------- edge scatter ----------------
__device__ __forceinline__ void red_add_v4(float* p, float a, float b, float c, float d) {
    asm volatile("red.global.add.v4.f32 [%0], {%1,%2,%3,%4};"
                 :: "l"(p), "f"(a), "f"(b), "f"(c), "f"(d) : "memory");
}

__global__ __launch_bounds__(256) void k_scatter(
    const float* __restrict__ H, float* __restrict__ O,
    const int* __restrict__ src, const int* __restrict__ dst, int E)
{
    int warp = (blockIdx.x * blockDim.x + threadIdx.x) >> 5;
    int lane = threadIdx.x & 31;
    if (warp >= E) return;
    int s = src[warp];
    int d = dst[warp];
    float nrm = g_dinv[s] * g_dinv[d];
    float4 v = ((const float4*)(H + (size_t)s * D128))[lane];
    float* p = O + (size_t)d * D128 + lane * 4;
    red_add_v4(p, v.x * nrm, v.y * nrm, v.z * nrm, v.w * nrm);
}

// ---------------- BatchNorm ----------------
__global__ __launch_bounds__(256) void k_bnreduce(const float* __restrict__ H, int N) {
    int f    = threadIdx.x & 127;
    int half = threadIdx.x >> 7;
    float s = 0.f, s2 = 0.f;
    for (int row = blockIdx.x * 2 + half; row < N; row += gridDim.x * 2) {
        float v = H[(size_t)row * D128 + f];
        s += v;
        s2 = fmaf(v, v, s2);
    }
    __shared__ float sh[256], sh2[256];
    sh[threadIdx.x] = s; sh2[threadIdx.x] = s2;
    __syncthreads();
    if (threadIdx.x < 128) {
        atomicAdd(&g_sum[f],   sh[f] + sh[f + 128]);
        atomicAdd(&g_sumsq[f], sh2[f] + sh2[f + 128]);
    }
}

__global__ void k_bnfinal(const float* __restrict__ gamma, const float* __restrict__ beta, int N) {
    int f = threadIdx.x;
    if (f >= D128) return;
    float inv_n = 1.0f / (float)N;
    float mu  = g_sum[f] * inv_n;
    float var = g_sumsq[f] * inv_n - mu * mu;
    float rstd = rsqrtf(var + 1e-5f);
    float s = rstd * gamma[f];
    g_scale[f] = s;
    g_bias[f]  = beta[f] - mu * s;
}

// ---------------- launch ----------------
extern "C" void kernel_launch(void* const* d_in, const int* in_sizes, int n_in,
                              void* d_out, int out_size)
{
    const float* x     = (const float*)d_in[0];
    const int*   eidx  = (const int*)d_in[1];
    const float* W1    = (const float*)d_in[2];
    const float* b1    = (const float*)d_in[3];
    const float* gamma = (const float*)d_in[4];
    const float* beta  = (const float*)d_in[5];
    const float* W2    = (const float*)d_in[6];
    const float* b2    = (const float*)d_in[7];
    float*       out   = (float*)d_out;

    const int N = in_sizes[0] / D128;          // 50000
    const int E = in_sizes[1] / 2;             // 800000
    const int* src = eidx;
    const int* dst = eidx + E;

    float* H;  cudaGetSymbolAddress((void**)&H,  g_H);
    float* O1; cudaGetSymbolAddress((void**)&O1, g_O1);
    float* scl; cudaGetSymbolAddress((void**)&scl, g_scale);
    float* bia; cudaGetSymbolAddress((void**)&bia, g_bias);

    const int GEMM_SMEM = (256 * WSTR + 128 * WSTR) * 4;   // 104448 B
    cudaFuncSetAttribute(k_gemm_tc, cudaFuncAttributeMaxDynamicSharedMemorySize, GEMM_SMEM);

    const int TPB = 256;
    int gridN  = (N + TPB - 1) / TPB;
    int gridE  = (E + TPB - 1) / TPB;
    long long lanes = (long long)E * 32;
    int gridEw = (int)((lanes + TPB - 1) / TPB);
    int gridG  = (N + 63) / 64;

    k_init<<<gridN, TPB>>>(N);
    k_deg<<<gridE, TPB>>>(dst, E);
    k_dinv<<<gridN, TPB>>>(N);
    k_wsplit2<<<64, 256>>>(W1, W2);

    // layer 1
    k_gemm_tc<<<gridG, 128, GEMM_SMEM>>>(x, H, O1, b1, N, 0, nullptr, nullptr);
    k_scatter<<<gridEw, TPB>>>(H, O1, src, dst, E);

    // batchnorm stats -> scale/bias
    k_bnreduce<<<256, TPB>>>(O1, N);
    k_bnfinal<<<1, 128>>>(gamma, beta, N);

    // layer 2 (BN+ReLU fused into A load)
    k_gemm_tc<<<gridG, 128, GEMM_SMEM>>>(O1, H, out, b2, N, 1, scl, bia);
    k_scatter<<<gridEw, TPB>>>(H, out, src, dst, E);
}

// round 8
// speedup vs baseline: 1.8895x; 1.6202x over previous
#include <cuda_runtime.h>
#include <cuda_bf16.h>
#include <cstdint>

#define D128 128
#define MAXN 50000
#define MAXE 800000
#define WSTR 68               // padded word stride (64 k-pair words + 4 pad)
#define SCAN_TPB 256
#define SCAN_BLOCKS ((MAXN + SCAN_TPB - 1) / SCAN_TPB)   // 196

// ---------------- scratch ----------------
__device__ float    g_H[MAXN * D128];
__device__ float    g_O1[MAXN * D128];
__device__ int      g_deg[MAXN];        // real in-degree (no self loop)
__device__ float    g_dinv[MAXN];       // rsqrt(deg+1)
__device__ int      g_rowstart[MAXN];
__device__ int      g_cursor[MAXN];
__device__ int      g_csrc[MAXE];
__device__ int      g_blocksum[SCAN_TPB];
__device__ float    g_sum[D128];
__device__ float    g_sumsq[D128];
__device__ float    g_scale[D128];
__device__ float    g_bias[D128];
__device__ uint32_t g_Wth[2 * 128 * 64];  // W^T hi bf16 k-pair packed [slot][n][p]
__device__ uint32_t g_Wtl[2 * 128 * 64];  // W^T lo

// ---------------- helpers ----------------
__device__ __forceinline__ uint32_t pack_bf16(float f0, float f1) {
    __nv_bfloat162 h = __floats2bfloat162_rn(f0, f1);
    return *reinterpret_cast<uint32_t*>(&h);
}

// ---------------- init / degree / dinv ----------------
__global__ void k_init(int N) {
    int i = blockIdx.x * blockDim.x + threadIdx.x;
    if (i < N) g_deg[i] = 0;
    if (i < D128) { g_sum[i] = 0.f; g_sumsq[i] = 0.f; }
}
__global__ void k_deg(const int* __restrict__ dst, int E) {
    int e = blockIdx.x * blockDim.x + threadIdx.x;
    if (e < E) atomicAdd(&g_deg[dst[e]], 1);
}
__global__ void k_dinv(int N) {
    int i = blockIdx.x * blockDim.x + threadIdx.x;
    if (i < N) g_dinv[i] = rsqrtf((float)(g_deg[i] + 1));
}

// ---------------- exclusive scan of g_deg -> g_rowstart (3 kernels) ----------------
__global__ void k_scan1(int N) {
    __shared__ int sh[SCAN_TPB];
    int t = threadIdx.x;
    int i = blockIdx.x * SCAN_TPB + t;
    int v = (i < N) ? g_deg[i] : 0;
    sh[t] = v;
    __syncthreads();
    // Hillis-Steele inclusive scan
    #pragma unroll
    for (int off = 1; off < SCAN_TPB; off <<= 1) {
        int add = (t >= off) ? sh[t - off] : 0;
        __syncthreads();
        sh[t] += add;
        __syncthreads();
    }
    if (i < N) g_rowstart[i] = sh[t] - v;       // local exclusive
    if (t == SCAN_TPB - 1) g_blocksum[blockIdx.x] = sh[t];
}
__global__ void k_scan2(int nblocks) {
    __shared__ int sh[SCAN_TPB];
    int t = threadIdx.x;
    int v = (t < nblocks) ? g_blocksum[t] : 0;
    sh[t] = v;
    __syncthreads();
    #pragma unroll
    for (int off = 1; off < SCAN_TPB; off <<= 1) {
        int add = (t >= off) ? sh[t - off] : 0;
        __syncthreads();
        sh[t] += add;
        __syncthreads();
    }
    g_blocksum[t] = sh[t] - v;                  // exclusive block offsets
}
__global__ void k_scan3(int N) {
    int i = blockIdx.x * blockDim.x + threadIdx.x;
    if (i >= N) return;
    int rs = g_rowstart[i] + g_blocksum[i / SCAN_TPB];
    g_rowstart[i] = rs;
    g_cursor[i]   = rs;
}
__global__ void k_fill(const int* __restrict__ src, const int* __restrict__ dst, int E) {
    int e = blockIdx.x * blockDim.x + threadIdx.x;
    if (e >= E) return;
    int d = dst[e];
    int pos = atomicAdd(&g_cursor[d], 1);
    g_csrc[pos] = src[e];
}

// ---------------- both W -> transposed bf16 hi/lo split ----------------
__global__ void k_wsplit2(const float* __restrict__ W1, const float* __restrict__ W2) {
    int idx = blockIdx.x * blockDim.x + threadIdx.x;
    if (idx >= 2 * 128 * 64) return;
    int slot = idx >> 13;
    int loc  = idx & 8191;
    int n = loc >> 6, p = loc & 63;
    const float* W = slot ? W2 : W1;
    float w0 = W[(2 * p) * D128 + n];
    float w1 = W[(2 * p + 1) * D128 + n];
    __nv_bfloat16 h0 = __float2bfloat16_rn(w0);
    __nv_bfloat16 h1 = __float2bfloat16_rn(w1);
    g_Wth[idx] = pack_bf16(__bfloat162float(h0), __bfloat162float(h1));
    g_Wtl[idx] = pack_bf16(w0 - __bfloat162float(h0), w1 - __bfloat162float(h1));
}

// ---------------- tensor-core GEMM (writes H only) ----------------
#define MMA3(accp, a0,a1,a2,a3, b0,b1) \
    asm volatile("mma.sync.aligned.m16n8k16.row.col.f32.bf16.bf16.f32 " \
        "{%0,%1,%2,%3}, {%4,%5,%6,%7}, {%8,%9}, {%0,%1,%2,%3};" \
        : "+f"((accp)[0]), "+f"((accp)[1]), "+f"((accp)[2]), "+f"((accp)[3]) \
        : "r"(a0), "r"(a1), "r"(a2), "r"(a3), "r"(b0), "r"(b1))

__global__ __launch_bounds__(128) void k_gemm_tc(
    const float* __restrict__ A, float* __restrict__ H,
    int N, int wslot,
    const float* __restrict__ scl, const float* __restrict__ bia)
{
    extern __shared__ uint32_t sm[];
    uint32_t* WH = sm;                 // [128][WSTR]
    uint32_t* WL = sm + 128 * WSTR;
    uint32_t* AH = sm + 256 * WSTR;    // [64][WSTR]
    uint32_t* AL = sm + 256 * WSTR + 64 * WSTR;

    const int tid  = threadIdx.x;
    const int brow = blockIdx.x * 64;

    {
        const uint4* Wg  = (const uint4*)(g_Wth + wslot * 8192);
        const uint4* Wg2 = (const uint4*)(g_Wtl + wslot * 8192);
        #pragma unroll
        for (int i = 0; i < 16; i++) {
            int v = tid + i * 128;
            int w = v * 4;
            int r = w >> 6, c = w & 63;
            uint4 q = Wg[v];
            uint32_t* p = WH + r * WSTR + c;
            p[0] = q.x; p[1] = q.y; p[2] = q.z; p[3] = q.w;
            uint4 q2 = Wg2[v];
            uint32_t* p2 = WL + r * WSTR + c;
            p2[0] = q2.x; p2[1] = q2.y; p2[2] = q2.z; p2[3] = q2.w;
        }
    }

    #pragma unroll
    for (int i = 0; i < 16; i++) {
        int v = tid + i * 128;
        int r = v >> 5, c4 = v & 31;
        int grow = brow + r;
        float4 x = make_float4(0.f, 0.f, 0.f, 0.f);
        if (grow < N) x = ((const float4*)(A + (size_t)grow * D128))[c4];
        if (scl != nullptr) {
            int f = c4 * 4;
            x.x = fmaxf(fmaf(x.x, scl[f + 0], bia[f + 0]), 0.f);
            x.y = fmaxf(fmaf(x.y, scl[f + 1], bia[f + 1]), 0.f);
            x.z = fmaxf(fmaf(x.z, scl[f + 2], bia[f + 2]), 0.f);
            x.w = fmaxf(fmaf(x.w, scl[f + 3], bia[f + 3]), 0.f);
        }
        __nv_bfloat16 hx = __float2bfloat16_rn(x.x);
        __nv_bfloat16 hy = __float2bfloat16_rn(x.y);
        __nv_bfloat16 hz = __float2bfloat16_rn(x.z);
        __nv_bfloat16 hw = __float2bfloat16_rn(x.w);
        int base = r * WSTR + 2 * c4;
        AH[base]     = pack_bf16(__bfloat162float(hx), __bfloat162float(hy));
        AH[base + 1] = pack_bf16(__bfloat162float(hz), __bfloat162float(hw));
        AL[base]     = pack_bf16(x.x - __bfloat162float(hx), x.y - __bfloat162float(hy));
        AL[base + 1] = pack_bf16(x.z - __bfloat162float(hz), x.w - __bfloat162float(hw));
    }
    __syncthreads();

    const int lane = tid & 31, warp = tid >> 5;
    const int g = lane >> 2, t = lane & 3;
    const int wrow = warp * 16;

    float acc[16][4];
    #pragma unroll
    for (int nt = 0; nt < 16; nt++)
        #pragma unroll
        for (int j = 0; j < 4; j++) acc[nt][j] = 0.f;

    #pragma unroll
    for (int ks = 0; ks < 8; ks++) {
        const int kp = ks * 8;
        uint32_t ah0 = AH[(wrow + g)     * WSTR + kp + t];
        uint32_t ah1 = AH[(wrow + g + 8) * WSTR + kp + t];
        uint32_t ah2 = AH[(wrow + g)     * WSTR + kp + t + 4];
        uint32_t ah3 = AH[(wrow + g + 8) * WSTR + kp + t + 4];
        uint32_t al0 = AL[(wrow + g)     * WSTR + kp + t];
        uint32_t al1 = AL[(wrow + g + 8) * WSTR + kp + t];
        uint32_t al2 = AL[(wrow + g)     * WSTR + kp + t + 4];
        uint32_t al3 = AL[(wrow + g + 8) * WSTR + kp + t + 4];
        #pragma unroll
        for (int nt = 0; nt < 16; nt++) {
            int n = nt * 8 + g;
            uint32_t bh0 = WH[n * WSTR + kp + t];
            uint32_t bh1 = WH[n * WSTR + kp + t + 4];
            uint32_t bl0 = WL[n * WSTR + kp + t];
            uint32_t bl1 = WL[n * WSTR + kp + t + 4];
            MMA3(acc[nt], ah0, ah1, ah2, ah3, bh0, bh1);
            MMA3(acc[nt], ah0, ah1, ah2, ah3, bl0, bl1);
            MMA3(acc[nt], al0, al1, al2, al3, bh0, bh1);
        }
    }

    const int r0 = brow + wrow + g;
    const int r1 = r0 + 8;
    #pragma unroll
    for (int nt = 0; nt < 16; nt++) {
        int col = nt * 8 + 2 * t;
        if (r0 < N)
            *(float2*)(H + (size_t)r0 * D128 + col) = make_float2(acc[nt][0], acc[nt][1]);
        if (r1 < N)
            *(float2*)(H + (size_t)r1 * D128 + col) = make_float2(acc[nt][2], acc[nt][3]);
    }
}

// ---------------- CSR gather aggregation ----------------
// warp per dst node: O[i] = bias + dinv_i^2*H[i] + sum_j dinv[s_j]*dinv_i*H[s_j]
__global__ __launch_bounds__(256) void k_agg(
    const float* __restrict__ H, float* __restrict__ O,
    const float* __restrict__ bias, int N)
{
    int node = (blockIdx.x * blockDim.x + threadIdx.x) >> 5;
    int lane = threadIdx.x & 31;
    if (node >= N) return;

    float di = g_dinv[node];
    float w  = di * di;

    float4 h = ((const float4*)(H + (size_t)node * D128))[lane];
    float4 acc;
    acc.x = h.x * w; acc.y = h.y * w; acc.z = h.z * w; acc.w = h.w * w;

    const int start = g_rowstart[node];
    const int cnt   = g_deg[node];
    const int* __restrict__ cs = g_csrc + start;

    int j = 0;
    for (; j + 2 <= cnt; j += 2) {
        int s0 = cs[j];
        int s1 = cs[j + 1];
        float n0 = g_dinv[s0] * di;
        float n1 = g_dinv[s1] * di;
        float4 v0 = ((const float4*)(H + (size_t)s0 * D128))[lane];
        float4 v1 = ((const float4*)(H + (size_t)s1 * D128))[lane];
        acc.x = fmaf(v0.x, n0, acc.x); acc.y = fmaf(v0.y, n0, acc.y);
        acc.z = fmaf(v0.z, n0, acc.z); acc.w = fmaf(v0.w, n0, acc.w);
        acc.x = fmaf(v1.x, n1, acc.x); acc.y = fmaf(v1.y, n1, acc.y);
        acc.z = fmaf(v1.z, n1, acc.z); acc.w = fmaf(v1.w, n1, acc.w);
    }
    if (j < cnt) {
        int s0 = cs[j];
        float n0 = g_dinv[s0] * di;
        float4 v0 = ((const float4*)(H + (size_t)s0 * D128))[lane];
        acc.x = fmaf(v0.x, n0, acc.x); acc.y = fmaf(v0.y, n0, acc.y);
        acc.z = fmaf(v0.z, n0, acc.z); acc.w = fmaf(v0.w, n0, acc.w);
    }

    float4 bb = ((const float4*)bias)[lane];
    acc.x += bb.x; acc.y += bb.y; acc.z += bb.z; acc.w += bb.w;
    ((float4*)(O + (size_t)node * D128))[lane] = acc;
}

// ---------------- BatchNorm ----------------
__global__ __launch_bounds__(256) void k_bnreduce(const float* __restrict__ H, int N) {
    int f    = threadIdx.x & 127;
    int half = threadIdx.x >> 7;
    float s = 0.f, s2 = 0.f;
    for (int row = blockIdx.x * 2 + half; row < N; row += gridDim.x * 2) {
        float v = H[(size_t)row * D128 + f];
        s += v;
        s2 = fmaf(v, v, s2);
    }
    __shared__ float sh[256], sh2[256];
    sh[threadIdx.x] = s; sh2[threadIdx.x] = s2;
    __syncthreads();
    if (threadIdx.x < 128) {
        atomicAdd(&g_sum[f],   sh[f] + sh[f + 128]);
        atomicAdd(&g_sumsq[f], sh2[f] + sh2[f + 128]);
    }
}
__global__ void k_bnfinal(const float* __restrict__ gamma, const float* __restrict__ beta, int N) {
    int f = threadIdx.x;
    if (f >= D128) return;
    float inv_n = 1.0f / (float)N;
    float mu  = g_sum[f] * inv_n;
    float var = g_sumsq[f] * inv_n - mu * mu;
    float rstd = rsqrtf(var + 1e-5f);
    float s = rstd * gamma[f];
    g_scale[f] = s;
    g_bias[f]  = beta[f] - mu * s;
}

// ---------------- launch ----------------
extern "C" void kernel_launch(void* const* d_in, const int* in_sizes, int n_in,
                              void* d_out, int out_size)
{
    const float* x     = (const float*)d_in[0];
    const int*   eidx  = (const int*)d_in[1];
    const float* W1    = (const float*)d_in[2];
    const float* b1    = (const float*)d_in[3];
    const float* gamma = (const float*)d_in[4];
    const float* beta  = (const float*)d_in[5];
    const float* W2    = (const float*)d_in[6];
    const float* b2    = (const float*)d_in[7];
    float*       out   = (float*)d_out;

    const int N = in_sizes[0] / D128;          // 50000
    const int E = in_sizes[1] / 2;             // 800000
    const int* src = eidx;
    const int* dst = eidx + E;

    float* H;  cudaGetSymbolAddress((void**)&H,  g_H);
    float* O1; cudaGetSymbolAddress((void**)&O1, g_O1);
    float* scl; cudaGetSymbolAddress((void**)&scl, g_scale);
    float* bia; cudaGetSymbolAddress((void**)&bia, g_bias);

    const int GEMM_SMEM = (256 * WSTR + 128 * WSTR) * 4;   // 104448 B
    cudaFuncSetAttribute(k_gemm_tc, cudaFuncAttributeMaxDynamicSharedMemorySize, GEMM_SMEM);

    const int TPB = 256;
    int gridN  = (N + TPB - 1) / TPB;
    int gridE  = (E + TPB - 1) / TPB;
    int gridG  = (N + 63) / 64;
    int gridA  = (N * 32 + TPB - 1) / TPB;     // warp per node
    int nscan  = (N + SCAN_TPB - 1) / SCAN_TPB;

    // graph structure (per call, deterministic)
    k_init<<<gridN, TPB>>>(N);
    k_deg<<<gridE, TPB>>>(dst, E);
    k_dinv<<<gridN, TPB>>>(N);
    k_scan1<<<nscan, SCAN_TPB>>>(N);
    k_scan2<<<1, SCAN_TPB>>>(nscan);
    k_scan3<<<gridN, TPB>>>(N);
    k_fill<<<gridE, TPB>>>(src, dst, E);
    k_wsplit2<<<64, 256>>>(W1, W2);

    // layer 1
    k_gemm_tc<<<gridG, 128, GEMM_SMEM>>>(x, H, N, 0, nullptr, nullptr);
    k_agg<<<gridA, TPB>>>(H, O1, b1, N);

    // batchnorm stats -> scale/bias
    k_bnreduce<<<256, TPB>>>(O1, N);
    k_bnfinal<<<1, 128>>>(gamma, beta, N);

    // layer 2 (BN+ReLU fused into A load)
    k_gemm_tc<<<gridG, 128, GEMM_SMEM>>>(O1, H, N, 1, scl, bia);
    k_agg<<<gridA, TPB>>>(H, out, b2, N);
}